// round 8
// baseline (speedup 1.0000x reference)
#include <cuda_runtime.h>

#define BB 64
#define VV 2000
#define FF 8
#define GG 80
#define NRR 5               // distinct mu_rho  (g = r*16 + t)
#define NTT 16              // distinct mu_theta
#define NROT 5
#define DD (FF*GG)          // 640
#define VCH 4               // vertex chunks per (b,k)
#define VCS (VV/VCH)        // 500
#define NSLICE 4
#define TPB (GG*NSLICE)     // 320 threads kernel A
#define TPBB 256            // kernel B: 32 j-lanes x 8 i-segments
#define JT 20               // j tiles of 32
#define BG 32               // b groups of 2
#define TWO_PI_F 6.283185307179586f
#define EPSF 1e-5f
#define NLOG2E -1.4426950408889634f

// partial (unnormalized) sums: [bk][chunk][9][G]  (0: sum w; 1..8: sum w*feat)
__device__ float g_part[BB*NROT][VCH][9][GG];

// ---------------- helpers ----------------
__device__ __forceinline__ unsigned long long pack2(float lo, float hi) {
    unsigned long long r;
    asm("mov.b64 %0, {%1, %2};" : "=l"(r) : "f"(lo), "f"(hi));
    return r;
}
__device__ __forceinline__ void fma2(unsigned long long& d,
                                     unsigned long long a, unsigned long long b) {
    asm("fma.rn.f32x2 %0, %1, %2, %3;" : "=l"(d) : "l"(a), "l"(b), "l"(d));
}
__device__ __forceinline__ void add2(unsigned long long& d, unsigned long long a) {
    asm("add.rn.f32x2 %0, %1, %2;" : "=l"(d) : "l"(d), "l"(a));
}
__device__ __forceinline__ float2 unpack2(unsigned long long v) {
    float lo, hi;
    asm("mov.b64 {%0, %1}, %2;" : "=f"(lo), "=f"(hi) : "l"(v));
    return make_float2(lo, hi);
}
__device__ __forceinline__ float ex2(float x) {   // matches __expf numerics
    float r;
    asm("ex2.approx.f32 %0, %1;" : "=f"(r) : "f"(x));
    return r;
}

// ---------------------------------------------------------------------------
// Kernel A: separable gaussians w[v, r*16+t] = Rm[v,r] * T[v,t].
// Staging: 21 exps/vertex, reciprocals pre-scaled by -log2e and hoisted
// (rho params in regs; theta params fixed per thread since 320 % 16 == 0).
// Inner loop per (v,g): 2 LDS + FMUL + FADD + pack + 4 FFMA2.
// ---------------------------------------------------------------------------
__global__ void __launch_bounds__(TPB)
gauss_desc_kernel(const float* __restrict__ feat,
                  const float* __restrict__ rho,
                  const float* __restrict__ theta,
                  const float* __restrict__ mask,
                  const float* __restrict__ mu_rho,
                  const float* __restrict__ sigma_rho,
                  const float* __restrict__ mu_theta,
                  const float* __restrict__ sigma_theta)
{
    extern __shared__ float sm[];
    float* s_T    = sm;               // [VCS*16]  32000 B
    float* s_Rm   = sm + VCS*NTT;     // [VCS*8]   16000 B (stride 8, r<5 used)
    float* s_feat = sm + VCS*24;      // [VCS*8]   16000 B
    float* s_thv  = sm + VCS*32;      // [VCS]      2000 B

    const int bk  = blockIdx.x;
    const int b   = bk / NROT;
    const int k   = bk % NROT;
    const int cv0 = blockIdx.y * VCS;
    const int tid = threadIdx.x;
    const float kdelta = (float)k * (TWO_PI_F / (float)NROT);

    // hoisted gaussian params
    float mur[NRR], nisr[NRR];
    #pragma unroll
    for (int r = 0; r < NRR; r++) {
        float m = mu_rho[r*NTT];                 // grid: constant across t
        float s = sigma_rho[r*NTT];
        mur[r]  = m;
        nisr[r] = NLOG2E / (s*s + EPSF);
    }
    const int t0 = tid & 15;                      // theta index this thread stages
    const float mut0  = mu_theta[t0];
    const float st0   = sigma_theta[t0];
    const float nist0 = NLOG2E / (st0*st0 + EPSF);

    // phase 1: per-vertex theta' + 5 rho gaussians * mask
    for (int v = tid; v < VCS; v += TPB) {
        float th = theta[b*VV + cv0 + v] + kdelta;
        if (th >= TWO_PI_F) th -= TWO_PI_F;       // theta in [0,2pi)
        s_thv[v] = th;
        float rr = rho[b*VV + cv0 + v];
        float mk = mask[b*VV + cv0 + v];
        #pragma unroll
        for (int r = 0; r < NRR; r++) {
            float d = rr - mur[r];
            s_Rm[v*8 + r] = ex2(d*d * nisr[r]) * mk;
        }
    }
    for (int i = tid; i < VCS*FF/4; i += TPB)
        ((float4*)s_feat)[i] = ((const float4*)(feat + (size_t)(b*VV + cv0)*FF))[i];
    __syncthreads();

    // phase 2: 16 theta gaussians per vertex (t fixed per thread)
    for (int i = tid; i < VCS*NTT; i += TPB) {
        int v = i >> 4;
        float d = s_thv[v] - mut0;
        s_T[i] = ex2(d*d * nist0);
    }
    __syncthreads();

    const int g     = tid % GG;
    const int slice = tid / GG;
    const int r     = g >> 4;
    const int t     = g & 15;

    float a0 = 0.0f;
    unsigned long long acc[4] = {0ull, 0ull, 0ull, 0ull};

    for (int v = slice; v < VCS; v += NSLICE) {
        float tv = s_T[v*NTT + t];
        float rv = s_Rm[v*8 + r];
        float w  = tv * rv;
        a0 += w;
        unsigned long long w2 = pack2(w, w);
        const ulonglong2* fp = (const ulonglong2*)(s_feat + v*FF);
        ulonglong2 q0 = fp[0];
        ulonglong2 q1 = fp[1];
        fma2(acc[0], w2, q0.x);
        fma2(acc[1], w2, q0.y);
        fma2(acc[2], w2, q1.x);
        fma2(acc[3], w2, q1.y);
    }
    __syncthreads();           // vertex data dead; overlay reduction

    float* red = sm;           // [9][TPB] = 11520 B (overlays s_T)
    red[0*TPB + tid] = a0;
    #pragma unroll
    for (int a = 0; a < 4; a++) {
        float2 u = unpack2(acc[a]);
        red[(1 + 2*a)*TPB + tid] = u.x;
        red[(2 + 2*a)*TPB + tid] = u.y;
    }
    __syncthreads();

    for (int e = tid; e < 9*GG; e += TPB) {
        int j  = e / GG;
        int gg = e - j*GG;
        float S = red[j*TPB + gg] + red[j*TPB + GG + gg]
                + red[j*TPB + 2*GG + gg] + red[j*TPB + 3*GG + gg];
        g_part[bk][blockIdx.y][j][gg] = S;
    }
}

// ---------------------------------------------------------------------------
// Kernel B: normalize, then out[b,j] = relu(max_k desc_k@W[:,j] + bias[j]).
// 640 blocks (20 j-tiles x 32 b-pairs) x 256 threads (32 j x 8 i-segments).
// 10 packed accs per thread; packed smem combine over the 8 segments.
// ---------------------------------------------------------------------------
__global__ void __launch_bounds__(TPBB)
gemm_max_relu_kernel(const float* __restrict__ Wm,
                     const float* __restrict__ bias,
                     float* __restrict__ out)
{
    __shared__ __align__(16) char smB[2*NROT*DD*4];    // 25600 B (union)
    float* s_desc = (float*)smB;                        // [2][5][640]
    unsigned long long* red = (unsigned long long*)smB; // [256][10] = 20480 B

    const int tid = threadIdx.x;
    const int b0  = blockIdx.y * 2;

    // chunk-sum + normalize descriptors for 2 b's x 5 rotations
    for (int e = tid; e < 2*NROT*GG; e += TPBB) {
        int bb = e / (NROT*GG);
        int rr = e - bb*(NROT*GG);
        int kk = rr / GG;
        int g  = rr - kk*GG;
        int bk = (b0 + bb)*NROT + kk;
        float S[9];
        #pragma unroll
        for (int j = 0; j < 9; j++) S[j] = 0.0f;
        #pragma unroll
        for (int c = 0; c < VCH; c++)
            #pragma unroll
            for (int j = 0; j < 9; j++) S[j] += g_part[bk][c][j][g];
        float inv = 1.0f / (S[0] + EPSF);
        #pragma unroll
        for (int f = 0; f < FF; f++)
            s_desc[(bb*NROT + kk)*DD + f*GG + g] = S[1 + f] * inv;
    }
    __syncthreads();

    const int tx  = tid & 31;
    const int seg = tid >> 5;                     // one segment per warp
    const int j   = blockIdx.x * 32 + tx;
    const int i0  = seg * (DD/8);                 // 80-row segment

    unsigned long long acc[10];
    #pragma unroll
    for (int a = 0; a < 10; a++) acc[a] = 0ull;

    #pragma unroll 5
    for (int i = i0; i < i0 + DD/8; i += 4) {
        float w0 = Wm[(i+0)*DD + j];
        float w1 = Wm[(i+1)*DD + j];
        float w2 = Wm[(i+2)*DD + j];
        float w3 = Wm[(i+3)*DD + j];
        unsigned long long wp0 = pack2(w0, w1);
        unsigned long long wp1 = pack2(w2, w3);
        #pragma unroll
        for (int a = 0; a < 10; a++) {
            ulonglong2 d = *(const ulonglong2*)&s_desc[a*DD + i];
            fma2(acc[a], d.x, wp0);
            fma2(acc[a], d.y, wp1);
        }
    }
    __syncthreads();                               // everyone done reading desc

    #pragma unroll
    for (int a = 0; a < 10; a++) red[tid*10 + a] = acc[a];
    __syncthreads();

    if (tid < 32) {
        const float bj = bias[j];
        #pragma unroll
        for (int bb = 0; bb < 2; bb++) {
            float m = -3.4e38f;
            #pragma unroll
            for (int kk = 0; kk < NROT; kk++) {
                int a = bb*NROT + kk;
                unsigned long long s = red[tid*10 + a];
                #pragma unroll
                for (int sg = 1; sg < 8; sg++)
                    add2(s, red[(sg*32 + tid)*10 + a]);
                float2 u = unpack2(s);
                m = fmaxf(m, u.x + u.y);
            }
            out[(b0 + bb)*DD + j] = fmaxf(m + bj, 0.0f);
        }
    }
}

// ---------------------------------------------------------------------------

extern "C" void kernel_launch(void* const* d_in, const int* in_sizes, int n_in,
                              void* d_out, int out_size) {
    const float* feat        = (const float*)d_in[0];
    const float* rho         = (const float*)d_in[1];
    const float* theta       = (const float*)d_in[2];
    const float* mask        = (const float*)d_in[3];
    const float* mu_rho      = (const float*)d_in[4];
    const float* sigma_rho   = (const float*)d_in[5];
    const float* mu_theta    = (const float*)d_in[6];
    const float* sigma_theta = (const float*)d_in[7];
    const float* Wm          = (const float*)d_in[8];
    const float* bias        = (const float*)d_in[9];
    float* out = (float*)d_out;

    const int smemA = (VCS*32 + VCS) * sizeof(float);   // 66000 B
    cudaFuncSetAttribute(gauss_desc_kernel,
                         cudaFuncAttributeMaxDynamicSharedMemorySize, smemA);

    gauss_desc_kernel<<<dim3(BB*NROT, VCH), TPB, smemA>>>(
        feat, rho, theta, mask, mu_rho, sigma_rho, mu_theta, sigma_theta);

    gemm_max_relu_kernel<<<dim3(JT, BG), TPBB>>>(Wm, bias, out);
}

// round 9
// speedup vs baseline: 1.0690x; 1.0690x over previous
#include <cuda_runtime.h>

#define BB 64
#define VV 2000
#define FF 8
#define GG 80
#define NRR 5               // distinct mu_rho  (g = r*16 + t)
#define NTT 16              // distinct mu_theta
#define NROT 5
#define DD (FF*GG)          // 640
#define VCH 8               // vertex chunks per (b,k)
#define VCS (VV/VCH)        // 250
#define NSLICE 4
#define TPB (GG*NSLICE)     // 320 threads kernel A
#define TPBB 256            // kernel B: 64 j-lanes x 4 i-segments
#define JT 10               // j tiles of 64
#define BG 32               // b groups of 2
#define TWO_PI_F 6.283185307179586f
#define EPSF 1e-5f
#define NLOG2E -1.4426950408889634f

// partial (unnormalized) sums: [bk][chunk][9][G]  (0: sum w; 1..8: sum w*feat)
__device__ float g_part[BB*NROT][VCH][9][GG];
// normalized descriptors: [bk][f*G+g]
__device__ __align__(16) float g_desc[BB*NROT][DD];

// ---------------- helpers ----------------
__device__ __forceinline__ unsigned long long pack2(float lo, float hi) {
    unsigned long long r;
    asm("mov.b64 %0, {%1, %2};" : "=l"(r) : "f"(lo), "f"(hi));
    return r;
}
__device__ __forceinline__ void fma2(unsigned long long& d,
                                     unsigned long long a, unsigned long long b) {
    asm("fma.rn.f32x2 %0, %1, %2, %3;" : "=l"(d) : "l"(a), "l"(b), "l"(d));
}
__device__ __forceinline__ void add2(unsigned long long& d, unsigned long long a) {
    asm("add.rn.f32x2 %0, %1, %2;" : "=l"(d) : "l"(d), "l"(a));
}
__device__ __forceinline__ float2 unpack2(unsigned long long v) {
    float lo, hi;
    asm("mov.b64 {%0, %1}, %2;" : "=f"(lo), "=f"(hi) : "l"(v));
    return make_float2(lo, hi);
}
__device__ __forceinline__ float ex2(float x) {
    float r;
    asm("ex2.approx.f32 %0, %1;" : "=f"(r) : "f"(x));
    return r;
}

// ---------------------------------------------------------------------------
// Kernel A: separable gaussians w[v, r*16+t] = Rm[v,r] * T[v,t].
// 21 ex2 per vertex staged in smem; inner loop per (v,g):
// 2 LDS + FMUL + FADD + pack + 4 FFMA2. VCH=8 -> 33KB smem, 4 blocks/SM.
// ---------------------------------------------------------------------------
__global__ void __launch_bounds__(TPB)
gauss_desc_kernel(const float* __restrict__ feat,
                  const float* __restrict__ rho,
                  const float* __restrict__ theta,
                  const float* __restrict__ mask,
                  const float* __restrict__ mu_rho,
                  const float* __restrict__ sigma_rho,
                  const float* __restrict__ mu_theta,
                  const float* __restrict__ sigma_theta)
{
    extern __shared__ float sm[];
    float* s_T    = sm;               // [VCS*16]  16000 B
    float* s_Rm   = sm + VCS*NTT;     // [VCS*8]    8000 B (stride 8, r<5 used)
    float* s_feat = sm + VCS*24;      // [VCS*8]    8000 B
    float* s_thv  = sm + VCS*32;      // [VCS]      1000 B

    const int bk  = blockIdx.x;
    const int b   = bk / NROT;
    const int k   = bk % NROT;
    const int cv0 = blockIdx.y * VCS;
    const int tid = threadIdx.x;
    const float kdelta = (float)k * (TWO_PI_F / (float)NROT);

    // hoisted gaussian params
    float mur[NRR], nisr[NRR];
    #pragma unroll
    for (int r = 0; r < NRR; r++) {
        float m = mu_rho[r*NTT];                 // grid: constant across t
        float s = sigma_rho[r*NTT];
        mur[r]  = m;
        nisr[r] = NLOG2E / (s*s + EPSF);
    }
    const int t0 = tid & 15;
    const float mut0  = mu_theta[t0];
    const float st0   = sigma_theta[t0];
    const float nist0 = NLOG2E / (st0*st0 + EPSF);

    // phase 1: per-vertex theta' + 5 rho gaussians * mask
    for (int v = tid; v < VCS; v += TPB) {
        float th = theta[b*VV + cv0 + v] + kdelta;
        if (th >= TWO_PI_F) th -= TWO_PI_F;       // theta in [0,2pi)
        s_thv[v] = th;
        float rr = rho[b*VV + cv0 + v];
        float mk = mask[b*VV + cv0 + v];
        #pragma unroll
        for (int r = 0; r < NRR; r++) {
            float d = rr - mur[r];
            s_Rm[v*8 + r] = ex2(d*d * nisr[r]) * mk;
        }
    }
    for (int i = tid; i < VCS*FF/4; i += TPB)
        ((float4*)s_feat)[i] = ((const float4*)(feat + (size_t)(b*VV + cv0)*FF))[i];
    __syncthreads();

    // phase 2: 16 theta gaussians per vertex (t fixed per thread)
    for (int i = tid; i < VCS*NTT; i += TPB) {
        int v = i >> 4;
        float d = s_thv[v] - mut0;
        s_T[i] = ex2(d*d * nist0);
    }
    __syncthreads();

    const int g     = tid % GG;
    const int slice = tid / GG;
    const int r     = g >> 4;
    const int t     = g & 15;

    float a0 = 0.0f;
    unsigned long long acc[4] = {0ull, 0ull, 0ull, 0ull};

    for (int v = slice; v < VCS; v += NSLICE) {
        float tv = s_T[v*NTT + t];
        float rv = s_Rm[v*8 + r];
        float w  = tv * rv;
        a0 += w;
        unsigned long long w2 = pack2(w, w);
        const ulonglong2* fp = (const ulonglong2*)(s_feat + v*FF);
        ulonglong2 q0 = fp[0];
        ulonglong2 q1 = fp[1];
        fma2(acc[0], w2, q0.x);
        fma2(acc[1], w2, q0.y);
        fma2(acc[2], w2, q1.x);
        fma2(acc[3], w2, q1.y);
    }
    __syncthreads();           // vertex data dead; overlay reduction

    float* red = sm;           // [9][TPB] = 11520 B
    red[0*TPB + tid] = a0;
    #pragma unroll
    for (int a = 0; a < 4; a++) {
        float2 u = unpack2(acc[a]);
        red[(1 + 2*a)*TPB + tid] = u.x;
        red[(2 + 2*a)*TPB + tid] = u.y;
    }
    __syncthreads();

    for (int e = tid; e < 9*GG; e += TPB) {
        int j  = e / GG;
        int gg = e - j*GG;
        float S = red[j*TPB + gg] + red[j*TPB + GG + gg]
                + red[j*TPB + 2*GG + gg] + red[j*TPB + 3*GG + gg];
        g_part[bk][blockIdx.y][j][gg] = S;
    }
}

// ---------------------------------------------------------------------------
// Kernel A2: reduce chunks + normalize ONCE: g_part -> g_desc[bk][f*G+g].
// ---------------------------------------------------------------------------
__global__ void __launch_bounds__(GG)
normalize_kernel()
{
    const int bk = blockIdx.x;
    const int g  = threadIdx.x;
    float S[9];
    #pragma unroll
    for (int j = 0; j < 9; j++) S[j] = 0.0f;
    #pragma unroll
    for (int c = 0; c < VCH; c++)
        #pragma unroll
        for (int j = 0; j < 9; j++) S[j] += g_part[bk][c][j][g];
    float inv = 1.0f / (S[0] + EPSF);
    #pragma unroll
    for (int f = 0; f < FF; f++)
        g_desc[bk][f*GG + g] = S[1 + f] * inv;
}

// ---------------------------------------------------------------------------
// Kernel B: out[b,j] = relu(max_k desc_k@W[:,j] + bias[j]).
// 320 blocks (10 j-tiles x 32 b-pairs) x 256 threads (64 j x 4 i-segments).
// Prologue is now a contiguous 25.6KB copy (10 desc rows are contiguous).
// ---------------------------------------------------------------------------
__global__ void __launch_bounds__(TPBB)
gemm_max_relu_kernel(const float* __restrict__ Wm,
                     const float* __restrict__ bias,
                     float* __restrict__ out)
{
    __shared__ __align__(16) char smB[2*NROT*DD*4];    // 25600 B (union)
    float* s_desc = (float*)smB;                        // [10][640]
    unsigned long long* red = (unsigned long long*)smB; // [256][10] = 20480 B

    const int tid = threadIdx.x;
    const int b0  = blockIdx.y * 2;

    // rows bk = b0*5 .. b0*5+9 are contiguous in g_desc
    {
        const float4* src = (const float4*)g_desc[b0*NROT];
        float4* dst = (float4*)s_desc;
        for (int e = tid; e < 2*NROT*DD/4; e += TPBB)
            dst[e] = src[e];
    }
    __syncthreads();

    const int tx  = tid & 63;
    const int seg = tid >> 6;
    const int j   = blockIdx.x * 64 + tx;
    const int i0  = seg * (DD/4);                 // 160-row segment

    unsigned long long acc[10];
    #pragma unroll
    for (int a = 0; a < 10; a++) acc[a] = 0ull;

    #pragma unroll 8
    for (int i = i0; i < i0 + DD/4; i += 4) {
        float w0 = Wm[(i+0)*DD + j];
        float w1 = Wm[(i+1)*DD + j];
        float w2 = Wm[(i+2)*DD + j];
        float w3 = Wm[(i+3)*DD + j];
        unsigned long long wp0 = pack2(w0, w1);
        unsigned long long wp1 = pack2(w2, w3);
        #pragma unroll
        for (int a = 0; a < 10; a++) {
            ulonglong2 d = *(const ulonglong2*)&s_desc[a*DD + i];
            fma2(acc[a], d.x, wp0);
            fma2(acc[a], d.y, wp1);
        }
    }
    __syncthreads();                               // everyone done reading desc

    #pragma unroll
    for (int a = 0; a < 10; a++) red[tid*10 + a] = acc[a];
    __syncthreads();

    if (tid < 64) {
        const float bj = bias[j];
        #pragma unroll
        for (int bb = 0; bb < 2; bb++) {
            float m = -3.4e38f;
            #pragma unroll
            for (int kk = 0; kk < NROT; kk++) {
                int a = bb*NROT + kk;
                unsigned long long s = red[tid*10 + a];
                add2(s, red[(64  + tid)*10 + a]);
                add2(s, red[(128 + tid)*10 + a]);
                add2(s, red[(192 + tid)*10 + a]);
                float2 u = unpack2(s);
                m = fmaxf(m, u.x + u.y);
            }
            out[(b0 + bb)*DD + j] = fmaxf(m + bj, 0.0f);
        }
    }
}

// ---------------------------------------------------------------------------

extern "C" void kernel_launch(void* const* d_in, const int* in_sizes, int n_in,
                              void* d_out, int out_size) {
    const float* feat        = (const float*)d_in[0];
    const float* rho         = (const float*)d_in[1];
    const float* theta       = (const float*)d_in[2];
    const float* mask        = (const float*)d_in[3];
    const float* mu_rho      = (const float*)d_in[4];
    const float* sigma_rho   = (const float*)d_in[5];
    const float* mu_theta    = (const float*)d_in[6];
    const float* sigma_theta = (const float*)d_in[7];
    const float* Wm          = (const float*)d_in[8];
    const float* bias        = (const float*)d_in[9];
    float* out = (float*)d_out;

    const int smemA = (VCS*32 + VCS) * sizeof(float);   // 33000 B
    cudaFuncSetAttribute(gauss_desc_kernel,
                         cudaFuncAttributeMaxDynamicSharedMemorySize, smemA);

    gauss_desc_kernel<<<dim3(BB*NROT, VCH), TPB, smemA>>>(
        feat, rho, theta, mask, mu_rho, sigma_rho, mu_theta, sigma_theta);

    normalize_kernel<<<BB*NROT, GG>>>();

    gemm_max_relu_kernel<<<dim3(JT, BG), TPBB>>>(Wm, bias, out);
}